// round 2
// baseline (speedup 1.0000x reference)
#include <cuda_runtime.h>
#include <cuda_bf16.h>
#include <math.h>

// Problem constants
#define B_SZ 8
#define L_SZ 1024
#define DM 1024
#define NH 16
#define NG 4
#define HD 64
#define QKV_E 1536
#define MROWS (B_SZ * L_SZ)   // 8192

// ---------------- scratch (device globals; no allocation allowed) ----------
__device__ float g_qkv[MROWS * QKV_E];            // 50.3 MB
__device__ float g_q[B_SZ * NH * L_SZ * HD];      // 33.5 MB  [b,h,l,d]
__device__ float g_k[B_SZ * NG * L_SZ * HD];      // 8.4 MB   [b,g,l,d]
__device__ float g_v[B_SZ * NG * L_SZ * HD];      // 8.4 MB   [b,g,l,d]
__device__ float g_attn[MROWS * DM];              // 33.5 MB  [b,l, h*64+d]

// ============================================================================
// Kernel 1/4: C[M,N] = A[M,K] @ W[N,K]^T   (both row-major)
// 128x128 block tile, BK=16, 256 threads, 8x8 micro-tile.
// ============================================================================
__global__ void __launch_bounds__(256) sgemm_nt_kernel(
    const float* __restrict__ A, const float* __restrict__ W,
    float* __restrict__ C, int M, int N, int K)
{
    __shared__ float As[16][128];
    __shared__ float Ws[16][128];

    const int tid = threadIdx.x;
    const int tx = tid & 15;
    const int ty = tid >> 4;
    const int m0 = blockIdx.y * 128;
    const int n0 = blockIdx.x * 128;

    const int lr = tid >> 2;          // 0..63
    const int lc = (tid & 3) << 2;    // 0,4,8,12

    float acc[8][8];
#pragma unroll
    for (int i = 0; i < 8; i++)
#pragma unroll
        for (int j = 0; j < 8; j++) acc[i][j] = 0.f;

    const float* Aptr = A + (size_t)(m0 + lr) * K + lc;
    const float* Wptr = W + (size_t)(n0 + lr) * K + lc;

    for (int k0 = 0; k0 < K; k0 += 16) {
        float4 a0 = *(const float4*)(Aptr + k0);
        float4 a1 = *(const float4*)(Aptr + (size_t)64 * K + k0);
        float4 w0 = *(const float4*)(Wptr + k0);
        float4 w1 = *(const float4*)(Wptr + (size_t)64 * K + k0);
        __syncthreads();
        As[lc + 0][lr] = a0.x; As[lc + 1][lr] = a0.y;
        As[lc + 2][lr] = a0.z; As[lc + 3][lr] = a0.w;
        As[lc + 0][lr + 64] = a1.x; As[lc + 1][lr + 64] = a1.y;
        As[lc + 2][lr + 64] = a1.z; As[lc + 3][lr + 64] = a1.w;
        Ws[lc + 0][lr] = w0.x; Ws[lc + 1][lr] = w0.y;
        Ws[lc + 2][lr] = w0.z; Ws[lc + 3][lr] = w0.w;
        Ws[lc + 0][lr + 64] = w1.x; Ws[lc + 1][lr + 64] = w1.y;
        Ws[lc + 2][lr + 64] = w1.z; Ws[lc + 3][lr + 64] = w1.w;
        __syncthreads();
#pragma unroll
        for (int k = 0; k < 16; k++) {
            float4 af0 = *(const float4*)&As[k][ty * 8];
            float4 af1 = *(const float4*)&As[k][ty * 8 + 4];
            float4 wf0 = *(const float4*)&Ws[k][tx * 8];
            float4 wf1 = *(const float4*)&Ws[k][tx * 8 + 4];
            float a[8] = {af0.x, af0.y, af0.z, af0.w, af1.x, af1.y, af1.z, af1.w};
            float w[8] = {wf0.x, wf0.y, wf0.z, wf0.w, wf1.x, wf1.y, wf1.z, wf1.w};
#pragma unroll
            for (int i = 0; i < 8; i++)
#pragma unroll
                for (int j = 0; j < 8; j++)
                    acc[i][j] = fmaf(a[i], w[j], acc[i][j]);
        }
    }

#pragma unroll
    for (int i = 0; i < 8; i++) {
        float4 o0 = make_float4(acc[i][0], acc[i][1], acc[i][2], acc[i][3]);
        float4 o1 = make_float4(acc[i][4], acc[i][5], acc[i][6], acc[i][7]);
        float* Cp = C + (size_t)(m0 + ty * 8 + i) * N + n0 + tx * 8;
        *(float4*)(Cp) = o0;
        *(float4*)(Cp + 4) = o1;
    }
}

// ============================================================================
// Kernel 2: qk-norm + RoPE2D + scale(q) + transpose to [b,head,l,d]
// One warp per head-vector (64 dims); lane owns dims {2*lane, 2*lane+1}.
// ============================================================================
__global__ void __launch_bounds__(256) norm_rope_kernel(
    const float* __restrict__ qkv,
    float* __restrict__ qo, float* __restrict__ ko, float* __restrict__ vo)
{
    const int gwarp = (blockIdx.x * blockDim.x + threadIdx.x) >> 5;
    const int lane = threadIdx.x & 31;
    const int NVEC = MROWS * 24;
    if (gwarp >= NVEC) return;

    const int bl = gwarp / 24;
    const int slot = gwarp % 24;
    const int b = bl >> 10;
    const int l = bl & 1023;

    const float2 xv = *(const float2*)(qkv + (size_t)bl * QKV_E + slot * 64 + 2 * lane);
    float x1 = xv.x, x2 = xv.y;

    if (slot < 20) {
        // L2 norm over 64 dims
        float ss = x1 * x1 + x2 * x2;
#pragma unroll
        for (int o = 16; o > 0; o >>= 1)
            ss += __shfl_xor_sync(0xffffffffu, ss, o);
        float inv = 1.f / (sqrtf(ss) + 1e-10f);
        if (slot < 16) inv *= 0.125f;   // fold 1/sqrt(HD) into q
        x1 *= inv; x2 *= inv;

        // RoPE2D: freq = (h_idx + w_idx) * theta^(-2*lane/64)
        float psum = (float)((l >> 5) + (l & 31));
        float invfreq = exp2f(-0.41524101186098287f * (float)lane);
        float fr = psum * invfreq;
        float s, c;
        sincosf(fr, &s, &c);
        float olo = x1 * c - x2 * s;
        float ohi = x1 * s + x2 * c;

        float* dst;
        if (slot < 16)
            dst = qo + (((size_t)b * NH + slot) * L_SZ + l) * HD;
        else
            dst = ko + (((size_t)b * NG + (slot - 16)) * L_SZ + l) * HD;
        dst[lane] = olo;
        dst[lane + 32] = ohi;
    } else {
        float* dst = vo + (((size_t)b * NG + (slot - 20)) * L_SZ + l) * HD;
        *(float2*)(dst + 2 * lane) = xv;
    }
}

// ============================================================================
// Kernel 3: flash attention, fp32.
// Block = (qtile of 64 rows, head, batch), 256 threads.
// Qs/Ks stored d-major (transposed) for float4 fragment loads.
// ============================================================================
#define QPAD 68
__global__ void __launch_bounds__(256) attn_kernel(
    const float* __restrict__ Q, const float* __restrict__ Kt,
    const float* __restrict__ Vt, float* __restrict__ O)
{
    extern __shared__ float sm[];
    float* Qs = sm;                       // [64][QPAD] indexed [d][row]
    float* Ks = Qs + 64 * QPAD;           // [64][QPAD] indexed [d][kcol]
    float* Vs = Ks + 64 * QPAD;           // [64][64]   indexed [k][d]
    float* Ss = Vs + 64 * 64;             // [64][QPAD] indexed [row][k]
    float* mrow = Ss + 64 * QPAD;         // [64]
    float* lrow = mrow + 64;              // [64]
    float* rrow = lrow + 64;              // [64]

    const int qt = blockIdx.x;
    const int h = blockIdx.y;
    const int b = blockIdx.z;
    const int g = h >> 2;                 // GQA: head h -> group h/4

    const int tid = threadIdx.x;
    const int tx = tid & 15;
    const int ty = tid >> 4;

    const float* Qg = Q + (((size_t)b * NH + h) * L_SZ + qt * 64) * HD;
    const float* Kg = Kt + (((size_t)b * NG + g) * L_SZ) * HD;
    const float* Vg = Vt + (((size_t)b * NG + g) * L_SZ) * HD;

    // load Q tile transposed into Qs[d][row]
    {
        const int r = tid >> 2;
        const int d0 = (tid & 3) << 4;
#pragma unroll
        for (int c = 0; c < 16; c += 4) {
            float4 v = *(const float4*)(Qg + (size_t)r * HD + d0 + c);
            Qs[(d0 + c + 0) * QPAD + r] = v.x;
            Qs[(d0 + c + 1) * QPAD + r] = v.y;
            Qs[(d0 + c + 2) * QPAD + r] = v.z;
            Qs[(d0 + c + 3) * QPAD + r] = v.w;
        }
    }
    if (tid < 64) { mrow[tid] = -INFINITY; lrow[tid] = 0.f; }

    float acc[4][4];
#pragma unroll
    for (int i = 0; i < 4; i++)
#pragma unroll
        for (int j = 0; j < 4; j++) acc[i][j] = 0.f;

    for (int k0 = 0; k0 < L_SZ; k0 += 64) {
        __syncthreads();   // previous tile's PV reads of Ks/Vs/Ss are done
        // load K tile transposed, V tile natural
        {
            const int r = tid >> 2;
            const int d0 = (tid & 3) << 4;
#pragma unroll
            for (int c = 0; c < 16; c += 4) {
                float4 kv = *(const float4*)(Kg + (size_t)(k0 + r) * HD + d0 + c);
                Ks[(d0 + c + 0) * QPAD + r] = kv.x;
                Ks[(d0 + c + 1) * QPAD + r] = kv.y;
                Ks[(d0 + c + 2) * QPAD + r] = kv.z;
                Ks[(d0 + c + 3) * QPAD + r] = kv.w;
                float4 vv = *(const float4*)(Vg + (size_t)(k0 + r) * HD + d0 + c);
                *(float4*)(Vs + r * 64 + d0 + c) = vv;
            }
        }
        __syncthreads();

        // S = Q @ K^T  (scale already folded into Q)
        float s[4][4];
#pragma unroll
        for (int i = 0; i < 4; i++)
#pragma unroll
            for (int j = 0; j < 4; j++) s[i][j] = 0.f;
#pragma unroll
        for (int d = 0; d < 64; d++) {
            float4 qa = *(const float4*)(Qs + d * QPAD + ty * 4);
            float4 kb = *(const float4*)(Ks + d * QPAD + tx * 4);
            float av[4] = {qa.x, qa.y, qa.z, qa.w};
            float bv[4] = {kb.x, kb.y, kb.z, kb.w};
#pragma unroll
            for (int i = 0; i < 4; i++)
#pragma unroll
                for (int j = 0; j < 4; j++)
                    s[i][j] = fmaf(av[i], bv[j], s[i][j]);
        }
#pragma unroll
        for (int i = 0; i < 4; i++)
            *(float4*)(Ss + (ty * 4 + i) * QPAD + tx * 4) =
                make_float4(s[i][0], s[i][1], s[i][2], s[i][3]);
        __syncthreads();

        // online softmax: one thread per q-row
        if (tid < 64) {
            float m_old = mrow[tid];
            float mx = m_old;
            float* srow = Ss + tid * QPAD;
#pragma unroll 8
            for (int c = 0; c < 64; c++) mx = fmaxf(mx, srow[c]);
            float resc = __expf(m_old - mx);   // 0 on first tile (m_old=-inf)
            float sum = 0.f;
#pragma unroll 8
            for (int c = 0; c < 64; c++) {
                float p = __expf(srow[c] - mx);
                srow[c] = p;
                sum += p;
            }
            mrow[tid] = mx;
            lrow[tid] = lrow[tid] * resc + sum;
            rrow[tid] = resc;
        }
        __syncthreads();

        // rescale accumulators, then acc += P @ V
        float rf[4];
#pragma unroll
        for (int i = 0; i < 4; i++) rf[i] = rrow[ty * 4 + i];
#pragma unroll
        for (int i = 0; i < 4; i++)
#pragma unroll
            for (int j = 0; j < 4; j++) acc[i][j] *= rf[i];

#pragma unroll
        for (int k = 0; k < 64; k++) {
            float4 vb = *(const float4*)(Vs + k * 64 + tx * 4);
            float vv[4] = {vb.x, vb.y, vb.z, vb.w};
            float p0 = Ss[(ty * 4 + 0) * QPAD + k];
            float p1 = Ss[(ty * 4 + 1) * QPAD + k];
            float p2 = Ss[(ty * 4 + 2) * QPAD + k];
            float p3 = Ss[(ty * 4 + 3) * QPAD + k];
#pragma unroll
            for (int j = 0; j < 4; j++) {
                acc[0][j] = fmaf(p0, vv[j], acc[0][j]);
                acc[1][j] = fmaf(p1, vv[j], acc[1][j]);
                acc[2][j] = fmaf(p2, vv[j], acc[2][j]);
                acc[3][j] = fmaf(p3, vv[j], acc[3][j]);
            }
        }
    }

    // final normalize + write to [b, l, h*64+d]
#pragma unroll
    for (int i = 0; i < 4; i++) {
        int r = ty * 4 + i;
        float invl = 1.f / lrow[r];
        int q = qt * 64 + r;
        float4 o = make_float4(acc[i][0] * invl, acc[i][1] * invl,
                               acc[i][2] * invl, acc[i][3] * invl);
        *(float4*)(O + ((size_t)(b * L_SZ + q)) * DM + h * 64 + tx * 4) = o;
    }
}

// ============================================================================
// launch
// ============================================================================
extern "C" void kernel_launch(void* const* d_in, const int* in_sizes, int n_in,
                              void* d_out, int out_size)
{
    const float* x     = (const float*)d_in[0];   // [8,1024,1024]
    const float* w_qkv = (const float*)d_in[1];   // [1536,1024]
    const float* w_o   = (const float*)d_in[2];   // [1024,1024]
    float* out = (float*)d_out;

    float *qkv_p, *q_p, *k_p, *v_p, *attn_p;
    cudaGetSymbolAddress((void**)&qkv_p,  g_qkv);
    cudaGetSymbolAddress((void**)&q_p,    g_q);
    cudaGetSymbolAddress((void**)&k_p,    g_k);
    cudaGetSymbolAddress((void**)&v_p,    g_v);
    cudaGetSymbolAddress((void**)&attn_p, g_attn);

    // 1) QKV projection: [8192,1536] = x[8192,1024] @ w_qkv^T
    {
        dim3 grid(QKV_E / 128, MROWS / 128);
        sgemm_nt_kernel<<<grid, 256>>>(x, w_qkv, qkv_p, MROWS, QKV_E, DM);
    }

    // 2) norm + rope + transpose
    {
        int nvec = MROWS * 24;          // head-vectors
        int nwarps_per_blk = 8;
        int blocks = (nvec + nwarps_per_blk - 1) / nwarps_per_blk;
        norm_rope_kernel<<<blocks, 256>>>(qkv_p, q_p, k_p, v_p);
    }

    // 3) attention
    {
        int smem = (3 * 64 * QPAD + 64 * 64 + 3 * 64) * (int)sizeof(float);
        cudaFuncSetAttribute(attn_kernel,
                             cudaFuncAttributeMaxDynamicSharedMemorySize, smem);
        dim3 grid(L_SZ / 64, NH, B_SZ);
        attn_kernel<<<grid, 256, smem>>>(q_p, k_p, v_p, attn_p);
    }

    // 4) output projection: [8192,1024] = attn[8192,1024] @ w_o^T
    {
        dim3 grid(DM / 128, MROWS / 128);
        sgemm_nt_kernel<<<grid, 256>>>(attn_p, w_o, out, MROWS, DM, DM);
    }
}

// round 4
// speedup vs baseline: 1.4592x; 1.4592x over previous
#include <cuda_runtime.h>
#include <cuda_bf16.h>
#include <math.h>
#include <stdint.h>

// Problem constants
#define B_SZ 8
#define L_SZ 1024
#define DM 1024
#define NH 16
#define NG 4
#define HD 64
#define QKV_E 1536
#define MROWS (B_SZ * L_SZ)   // 8192

// ---------------- scratch (device globals; no allocation allowed) ----------
__device__ float g_qkv[MROWS * QKV_E];
__device__ float g_q[B_SZ * NH * L_SZ * HD];
__device__ float g_k[B_SZ * NG * L_SZ * HD];
__device__ float g_v[B_SZ * NG * L_SZ * HD];
__device__ float g_attn[MROWS * DM];

// ============================================================================
// helpers
// ============================================================================
__device__ __forceinline__ uint32_t smem_u32(const void* p) {
    uint32_t a;
    asm("{ .reg .u64 t; cvta.to.shared.u64 t, %1; cvt.u32.u64 %0, t; }"
        : "=r"(a) : "l"(p));
    return a;
}

__device__ __forceinline__ void ldsm4(uint32_t* r, uint32_t addr) {
    asm volatile("ldmatrix.sync.aligned.m8n8.x4.shared.b16 {%0,%1,%2,%3}, [%4];"
        : "=r"(r[0]), "=r"(r[1]), "=r"(r[2]), "=r"(r[3]) : "r"(addr));
}

__device__ __forceinline__ void mma_bf16(float* d, const uint32_t* a,
                                         const uint32_t* b) {
    asm volatile(
        "mma.sync.aligned.m16n8k16.row.col.f32.bf16.bf16.f32 "
        "{%0,%1,%2,%3}, {%4,%5,%6,%7}, {%8,%9}, {%0,%1,%2,%3};"
        : "+f"(d[0]), "+f"(d[1]), "+f"(d[2]), "+f"(d[3])
        : "r"(a[0]), "r"(a[1]), "r"(a[2]), "r"(a[3]), "r"(b[0]), "r"(b[1]));
}

// split 8 consecutive fp32 into bf16 hi (uint4) and bf16 lo residual (uint4)
__device__ __forceinline__ void split8(const float4 v0, const float4 v1,
                                       uint4& hi, uint4& lo) {
    const float f[8] = {v0.x, v0.y, v0.z, v0.w, v1.x, v1.y, v1.z, v1.w};
    uint32_t h[4], l[4];
#pragma unroll
    for (int i = 0; i < 4; i++) {
        __nv_bfloat162 hh = __float22bfloat162_rn(make_float2(f[2*i], f[2*i+1]));
        float2 hf = __bfloat1622float2(hh);
        __nv_bfloat162 ll = __float22bfloat162_rn(
            make_float2(f[2*i] - hf.x, f[2*i+1] - hf.y));
        h[i] = *(uint32_t*)&hh;
        l[i] = *(uint32_t*)&ll;
    }
    hi = make_uint4(h[0], h[1], h[2], h[3]);
    lo = make_uint4(l[0], l[1], l[2], l[3]);
}

// ============================================================================
// Kernel 1/4: C[M,N] = A[M,K] @ W[N,K]^T via bf16x3 mma.sync (fp32 accuracy).
// 128x128 CTA tile, BK=32, 8 warps (4m x 2n), warp tile 32x64.
// smem per stage: Ah,Al,Wh,Wl each [128 rows][32 bf16] (64B rows), 2 stages.
// 16B-chunk swizzle: chunk' = chunk ^ ((row>>1)&3)  -> conflict-free ldmatrix.
// ============================================================================
#define GSTAGE_BYTES 32768           // 4 buffers x 8KB
#define GEMM_SMEM (2 * GSTAGE_BYTES) // 64KB

__global__ void __launch_bounds__(256, 1) gemm_bf16x3_kernel(
    const float* __restrict__ A, const float* __restrict__ W,
    float* __restrict__ C, int N, int K)
{
    extern __shared__ char smem[];
    const uint32_t sb = smem_u32(smem);
    const int tid = threadIdx.x;
    const int wid = tid >> 5;
    const int lane = tid & 31;
    const int m0 = blockIdx.y * 128;
    const int n0 = blockIdx.x * 128;
    const int NC = K >> 5;                       // BK=32 chunks

    const int warp_m = wid & 3;                  // 0..3 -> m offset *32
    const int warp_n = wid >> 2;                 // 0..1 -> n offset *64

    // ---- loader mapping: thread -> (row, 16-float column group) ----
    const int lrow = tid >> 1;                   // 0..127
    const int lcg = (tid & 1) * 16;              // 0 or 16
    const float* Ag = A + (size_t)(m0 + lrow) * K + lcg;
    const float* Wg = W + (size_t)(n0 + lrow) * K + lcg;
    // two 16B chunks per buffer (8 bf16 each)
    const int swz_l = (lrow >> 1) & 3;
    const uint32_t so0 = lrow * 64 + ((((tid & 1) * 2 + 0) ^ swz_l) << 4);
    const uint32_t so1 = lrow * 64 + ((((tid & 1) * 2 + 1) ^ swz_l) << 4);

    // ---- ldmatrix address precompute ----
    // A tiles (m16k16): row = warp_m*32 + tm*16 + (lane&15), chunk = ks*2 + (lane>>4)
    uint32_t aoff[2][2];  // [tm][ks]
#pragma unroll
    for (int tm = 0; tm < 2; tm++) {
        int r = warp_m * 32 + tm * 16 + (lane & 15);
        int sw = (r >> 1) & 3;
#pragma unroll
        for (int ks = 0; ks < 2; ks++) {
            int ch = ks * 2 + (lane >> 4);
            aoff[tm][ks] = r * 64 + ((ch ^ sw) << 4);
        }
    }
    // B pairs (2 n-tiles per ldmatrix.x4):
    // row = warp_n*64 + bp*16 + ((lane>>4)<<3) + (lane&7), chunk = ks*2 + ((lane>>3)&1)
    uint32_t boff[4][2];  // [bp][ks]
#pragma unroll
    for (int bp = 0; bp < 4; bp++) {
        int r = warp_n * 64 + bp * 16 + ((lane >> 4) << 3) + (lane & 7);
        int sw = (r >> 1) & 3;
#pragma unroll
        for (int ks = 0; ks < 2; ks++) {
            int ch = ks * 2 + ((lane >> 3) & 1);
            boff[bp][ks] = r * 64 + ((ch ^ sw) << 4);
        }
    }

    float acc[2][8][4];
#pragma unroll
    for (int i = 0; i < 2; i++)
#pragma unroll
        for (int j = 0; j < 8; j++)
#pragma unroll
            for (int q = 0; q < 4; q++) acc[i][j][q] = 0.f;

    float4 ra[4], rw[4];

    auto ldg_stage = [&](int s) {
        const float* ap = Ag + s * 32;
        const float* wp = Wg + s * 32;
#pragma unroll
        for (int j = 0; j < 4; j++) ra[j] = *(const float4*)(ap + 4 * j);
#pragma unroll
        for (int j = 0; j < 4; j++) rw[j] = *(const float4*)(wp + 4 * j);
    };
    auto sts_stage = [&](int buf) {
        const uint32_t base = sb + buf * GSTAGE_BYTES;
        uint4 hi, lo;
        split8(ra[0], ra[1], hi, lo);
        *(uint4*)(smem + (base - sb) + 0 + so0) = hi;
        *(uint4*)(smem + (base - sb) + 8192 + so0) = lo;
        split8(ra[2], ra[3], hi, lo);
        *(uint4*)(smem + (base - sb) + 0 + so1) = hi;
        *(uint4*)(smem + (base - sb) + 8192 + so1) = lo;
        split8(rw[0], rw[1], hi, lo);
        *(uint4*)(smem + (base - sb) + 16384 + so0) = hi;
        *(uint4*)(smem + (base - sb) + 24576 + so0) = lo;
        split8(rw[2], rw[3], hi, lo);
        *(uint4*)(smem + (base - sb) + 16384 + so1) = hi;
        *(uint4*)(smem + (base - sb) + 24576 + so1) = lo;
    };

    auto compute = [&](int buf) {
        const uint32_t ah = sb + buf * GSTAGE_BYTES;
        const uint32_t al = ah + 8192;
        const uint32_t wh = ah + 16384;
        const uint32_t wl = ah + 24576;
#pragma unroll
        for (int ks = 0; ks < 2; ks++) {
            uint32_t fa[2][4], fal[2][4];
#pragma unroll
            for (int tm = 0; tm < 2; tm++) {
                ldsm4(fa[tm], ah + aoff[tm][ks]);
                ldsm4(fal[tm], al + aoff[tm][ks]);
            }
            uint32_t fb[8][2], fbl[8][2];
#pragma unroll
            for (int bp = 0; bp < 4; bp++) {
                uint32_t t[4];
                ldsm4(t, wh + boff[bp][ks]);
                fb[2*bp][0] = t[0]; fb[2*bp][1] = t[1];
                fb[2*bp+1][0] = t[2]; fb[2*bp+1][1] = t[3];
                ldsm4(t, wl + boff[bp][ks]);
                fbl[2*bp][0] = t[0]; fbl[2*bp][1] = t[1];
                fbl[2*bp+1][0] = t[2]; fbl[2*bp+1][1] = t[3];
            }
#pragma unroll
            for (int tm = 0; tm < 2; tm++)
#pragma unroll
                for (int tn = 0; tn < 8; tn++) {
                    mma_bf16(acc[tm][tn], fa[tm], fb[tn]);   // hi*hi
                    mma_bf16(acc[tm][tn], fal[tm], fb[tn]);  // lo*hi
                    mma_bf16(acc[tm][tn], fa[tm], fbl[tn]);  // hi*lo
                }
        }
    };

    // ---- pipeline ----
    ldg_stage(0);
    sts_stage(0);
    if (NC > 1) ldg_stage(1);
    __syncthreads();

#pragma unroll 1
    for (int bk = 0; bk < NC; bk++) {
        const int buf = bk & 1;
        if (bk + 1 < NC) sts_stage(buf ^ 1);
        if (bk + 2 < NC) ldg_stage(bk + 2);
        compute(buf);
        __syncthreads();
    }

    // ---- epilogue ----
    const int er = lane >> 2;            // row within 8
    const int ec = (lane & 3) * 2;       // col within 8
#pragma unroll
    for (int tm = 0; tm < 2; tm++) {
        const int rbase = m0 + warp_m * 32 + tm * 16 + er;
#pragma unroll
        for (int tn = 0; tn < 8; tn++) {
            const int cbase = n0 + warp_n * 64 + tn * 8 + ec;
            float* p0 = C + (size_t)rbase * N + cbase;
            float* p1 = C + (size_t)(rbase + 8) * N + cbase;
            *(float2*)p0 = make_float2(acc[tm][tn][0], acc[tm][tn][1]);
            *(float2*)p1 = make_float2(acc[tm][tn][2], acc[tm][tn][3]);
        }
    }
}

// ============================================================================
// Kernel 2: qk-norm + RoPE2D + scale(q) + transpose to [b,head,l,d]
// ============================================================================
__global__ void __launch_bounds__(256) norm_rope_kernel(
    const float* __restrict__ qkv,
    float* __restrict__ qo, float* __restrict__ ko, float* __restrict__ vo)
{
    const int gwarp = (blockIdx.x * blockDim.x + threadIdx.x) >> 5;
    const int lane = threadIdx.x & 31;
    const int NVEC = MROWS * 24;
    if (gwarp >= NVEC) return;

    const int bl = gwarp / 24;
    const int slot = gwarp % 24;
    const int b = bl >> 10;
    const int l = bl & 1023;

    const float2 xv = *(const float2*)(qkv + (size_t)bl * QKV_E + slot * 64 + 2 * lane);
    float x1 = xv.x, x2 = xv.y;

    if (slot < 20) {
        float ss = x1 * x1 + x2 * x2;
#pragma unroll
        for (int o = 16; o > 0; o >>= 1)
            ss += __shfl_xor_sync(0xffffffffu, ss, o);
        float inv = 1.f / (sqrtf(ss) + 1e-10f);
        if (slot < 16) inv *= 0.125f;
        x1 *= inv; x2 *= inv;

        float psum = (float)((l >> 5) + (l & 31));
        float invfreq = exp2f(-0.41524101186098287f * (float)lane);
        float fr = psum * invfreq;
        float s, c;
        sincosf(fr, &s, &c);
        float olo = x1 * c - x2 * s;
        float ohi = x1 * s + x2 * c;

        float* dst;
        if (slot < 16)
            dst = qo + (((size_t)b * NH + slot) * L_SZ + l) * HD;
        else
            dst = ko + (((size_t)b * NG + (slot - 16)) * L_SZ + l) * HD;
        dst[lane] = olo;
        dst[lane + 32] = ohi;
    } else {
        float* dst = vo + (((size_t)b * NG + (slot - 20)) * L_SZ + l) * HD;
        *(float2*)(dst + 2 * lane) = xv;
    }
}

// ============================================================================
// Kernel 3: flash attention, fp32 (unchanged)
// ============================================================================
#define QPAD 68
__global__ void __launch_bounds__(256) attn_kernel(
    const float* __restrict__ Q, const float* __restrict__ Kt,
    const float* __restrict__ Vt, float* __restrict__ O)
{
    extern __shared__ float sm[];
    float* Qs = sm;
    float* Ks = Qs + 64 * QPAD;
    float* Vs = Ks + 64 * QPAD;
    float* Ss = Vs + 64 * 64;
    float* mrow = Ss + 64 * QPAD;
    float* lrow = mrow + 64;
    float* rrow = lrow + 64;

    const int qt = blockIdx.x;
    const int h = blockIdx.y;
    const int b = blockIdx.z;
    const int g = h >> 2;

    const int tid = threadIdx.x;
    const int tx = tid & 15;
    const int ty = tid >> 4;

    const float* Qg = Q + (((size_t)b * NH + h) * L_SZ + qt * 64) * HD;
    const float* Kg = Kt + (((size_t)b * NG + g) * L_SZ) * HD;
    const float* Vg = Vt + (((size_t)b * NG + g) * L_SZ) * HD;

    {
        const int r = tid >> 2;
        const int d0 = (tid & 3) << 4;
#pragma unroll
        for (int c = 0; c < 16; c += 4) {
            float4 v = *(const float4*)(Qg + (size_t)r * HD + d0 + c);
            Qs[(d0 + c + 0) * QPAD + r] = v.x;
            Qs[(d0 + c + 1) * QPAD + r] = v.y;
            Qs[(d0 + c + 2) * QPAD + r] = v.z;
            Qs[(d0 + c + 3) * QPAD + r] = v.w;
        }
    }
    if (tid < 64) { mrow[tid] = -INFINITY; lrow[tid] = 0.f; }

    float acc[4][4];
#pragma unroll
    for (int i = 0; i < 4; i++)
#pragma unroll
        for (int j = 0; j < 4; j++) acc[i][j] = 0.f;

    for (int k0 = 0; k0 < L_SZ; k0 += 64) {
        __syncthreads();
        {
            const int r = tid >> 2;
            const int d0 = (tid & 3) << 4;
#pragma unroll
            for (int c = 0; c < 16; c += 4) {
                float4 kv = *(const float4*)(Kg + (size_t)(k0 + r) * HD + d0 + c);
                Ks[(d0 + c + 0) * QPAD + r] = kv.x;
                Ks[(d0 + c + 1) * QPAD + r] = kv.y;
                Ks[(d0 + c + 2) * QPAD + r] = kv.z;
                Ks[(d0 + c + 3) * QPAD + r] = kv.w;
                float4 vv = *(const float4*)(Vg + (size_t)(k0 + r) * HD + d0 + c);
                *(float4*)(Vs + r * 64 + d0 + c) = vv;
            }
        }
        __syncthreads();

        float s[4][4];
#pragma unroll
        for (int i = 0; i < 4; i++)
#pragma unroll
            for (int j = 0; j < 4; j++) s[i][j] = 0.f;
#pragma unroll
        for (int d = 0; d < 64; d++) {
            float4 qa = *(const float4*)(Qs + d * QPAD + ty * 4);
            float4 kb = *(const float4*)(Ks + d * QPAD + tx * 4);
            float av[4] = {qa.x, qa.y, qa.z, qa.w};
            float bv[4] = {kb.x, kb.y, kb.z, kb.w};
#pragma unroll
            for (int i = 0; i < 4; i++)
#pragma unroll
                for (int j = 0; j < 4; j++)
                    s[i][j] = fmaf(av[i], bv[j], s[i][j]);
        }
#pragma unroll
        for (int i = 0; i < 4; i++)
            *(float4*)(Ss + (ty * 4 + i) * QPAD + tx * 4) =
                make_float4(s[i][0], s[i][1], s[i][2], s[i][3]);
        __syncthreads();

        if (tid < 64) {
            float m_old = mrow[tid];
            float mx = m_old;
            float* srow = Ss + tid * QPAD;
#pragma unroll 8
            for (int c = 0; c < 64; c++) mx = fmaxf(mx, srow[c]);
            float resc = __expf(m_old - mx);
            float sum = 0.f;
#pragma unroll 8
            for (int c = 0; c < 64; c++) {
                float p = __expf(srow[c] - mx);
                srow[c] = p;
                sum += p;
            }
            mrow[tid] = mx;
            lrow[tid] = lrow[tid] * resc + sum;
            rrow[tid] = resc;
        }
        __syncthreads();

        float rf[4];
#pragma unroll
        for (int i = 0; i < 4; i++) rf[i] = rrow[ty * 4 + i];
#pragma unroll
        for (int i = 0; i < 4; i++)
#pragma unroll
            for (int j = 0; j < 4; j++) acc[i][j] *= rf[i];

#pragma unroll
        for (int k = 0; k < 64; k++) {
            float4 vb = *(const float4*)(Vs + k * 64 + tx * 4);
            float vv[4] = {vb.x, vb.y, vb.z, vb.w};
            float p0 = Ss[(ty * 4 + 0) * QPAD + k];
            float p1 = Ss[(ty * 4 + 1) * QPAD + k];
            float p2 = Ss[(ty * 4 + 2) * QPAD + k];
            float p3 = Ss[(ty * 4 + 3) * QPAD + k];
#pragma unroll
            for (int j = 0; j < 4; j++) {
                acc[0][j] = fmaf(p0, vv[j], acc[0][j]);
                acc[1][j] = fmaf(p1, vv[j], acc[1][j]);
                acc[2][j] = fmaf(p2, vv[j], acc[2][j]);
                acc[3][j] = fmaf(p3, vv[j], acc[3][j]);
            }
        }
    }

#pragma unroll
    for (int i = 0; i < 4; i++) {
        int r = ty * 4 + i;
        float invl = 1.f / lrow[r];
        int q = qt * 64 + r;
        float4 o = make_float4(acc[i][0] * invl, acc[i][1] * invl,
                               acc[i][2] * invl, acc[i][3] * invl);
        *(float4*)(O + ((size_t)(b * L_SZ + q)) * DM + h * 64 + tx * 4) = o;
    }
}

// ============================================================================
// launch
// ============================================================================
extern "C" void kernel_launch(void* const* d_in, const int* in_sizes, int n_in,
                              void* d_out, int out_size)
{
    const float* x     = (const float*)d_in[0];
    const float* w_qkv = (const float*)d_in[1];
    const float* w_o   = (const float*)d_in[2];
    float* out = (float*)d_out;

    float *qkv_p, *q_p, *k_p, *v_p, *attn_p;
    cudaGetSymbolAddress((void**)&qkv_p,  g_qkv);
    cudaGetSymbolAddress((void**)&q_p,    g_q);
    cudaGetSymbolAddress((void**)&k_p,    g_k);
    cudaGetSymbolAddress((void**)&v_p,    g_v);
    cudaGetSymbolAddress((void**)&attn_p, g_attn);

    cudaFuncSetAttribute(gemm_bf16x3_kernel,
                         cudaFuncAttributeMaxDynamicSharedMemorySize, GEMM_SMEM);

    // 1) QKV projection: [8192,1536] = x @ w_qkv^T (bf16x3 tensor cores)
    {
        dim3 grid(QKV_E / 128, MROWS / 128);
        gemm_bf16x3_kernel<<<grid, 256, GEMM_SMEM>>>(x, w_qkv, qkv_p, QKV_E, DM);
    }

    // 2) norm + rope + transpose
    {
        int nvec = MROWS * 24;
        int blocks = (nvec + 7) / 8;
        norm_rope_kernel<<<blocks, 256>>>(qkv_p, q_p, k_p, v_p);
    }

    // 3) attention (fp32)
    {
        int smem = (3 * 64 * QPAD + 64 * 64 + 3 * 64) * (int)sizeof(float);
        cudaFuncSetAttribute(attn_kernel,
                             cudaFuncAttributeMaxDynamicSharedMemorySize, smem);
        dim3 grid(L_SZ / 64, NH, B_SZ);
        attn_kernel<<<grid, 256, smem>>>(q_p, k_p, v_p, attn_p);
    }

    // 4) output projection: [8192,1024] = attn @ w_o^T (bf16x3 tensor cores)
    {
        dim3 grid(DM / 128, MROWS / 128);
        gemm_bf16x3_kernel<<<grid, 256, GEMM_SMEM>>>(attn_p, w_o, out, DM, DM);
    }
}

// round 5
// speedup vs baseline: 2.8989x; 1.9866x over previous
#include <cuda_runtime.h>
#include <cuda_bf16.h>
#include <math.h>
#include <stdint.h>

// Problem constants
#define B_SZ 8
#define L_SZ 1024
#define DM 1024
#define NH 16
#define NG 4
#define HD 64
#define QKV_E 1536
#define MROWS (B_SZ * L_SZ)   // 8192

// ---------------- scratch (device globals; no allocation allowed) ----------
__device__ float g_qkv[MROWS * QKV_E];
__device__ float g_attn[MROWS * DM];
__device__ __nv_bfloat16 g_qh[B_SZ * NH * L_SZ * HD];
__device__ __nv_bfloat16 g_ql[B_SZ * NH * L_SZ * HD];
__device__ __nv_bfloat16 g_kh[B_SZ * NG * L_SZ * HD];
__device__ __nv_bfloat16 g_kl[B_SZ * NG * L_SZ * HD];
__device__ __nv_bfloat16 g_vth[B_SZ * NG * HD * L_SZ];  // [b,g,d,l]
__device__ __nv_bfloat16 g_vtl[B_SZ * NG * HD * L_SZ];

// ============================================================================
// helpers
// ============================================================================
__device__ __forceinline__ uint32_t smem_u32(const void* p) {
    uint32_t a;
    asm("{ .reg .u64 t; cvta.to.shared.u64 t, %1; cvt.u32.u64 %0, t; }"
        : "=r"(a) : "l"(p));
    return a;
}

__device__ __forceinline__ void ldsm4(uint32_t* r, uint32_t addr) {
    asm volatile("ldmatrix.sync.aligned.m8n8.x4.shared.b16 {%0,%1,%2,%3}, [%4];"
        : "=r"(r[0]), "=r"(r[1]), "=r"(r[2]), "=r"(r[3]) : "r"(addr));
}

__device__ __forceinline__ void mma_bf16(float* d, const uint32_t* a,
                                         const uint32_t* b) {
    asm volatile(
        "mma.sync.aligned.m16n8k16.row.col.f32.bf16.bf16.f32 "
        "{%0,%1,%2,%3}, {%4,%5,%6,%7}, {%8,%9}, {%0,%1,%2,%3};"
        : "+f"(d[0]), "+f"(d[1]), "+f"(d[2]), "+f"(d[3])
        : "r"(a[0]), "r"(a[1]), "r"(a[2]), "r"(a[3]), "r"(b[0]), "r"(b[1]));
}

// pack 2 floats -> bf16x2 hi, plus residual lo
__device__ __forceinline__ void split2(float a, float b, uint32_t& hi, uint32_t& lo) {
    __nv_bfloat162 h = __float22bfloat162_rn(make_float2(a, b));
    float2 hf = __bfloat1622float2(h);
    __nv_bfloat162 l = __float22bfloat162_rn(make_float2(a - hf.x, b - hf.y));
    hi = *(uint32_t*)&h;
    lo = *(uint32_t*)&l;
}

__device__ __forceinline__ void split1(float v, __nv_bfloat16& h, __nv_bfloat16& l) {
    h = __float2bfloat16(v);
    l = __float2bfloat16(v - __bfloat162float(h));
}

// split 8 consecutive fp32 into bf16 hi (uint4) and bf16 lo residual (uint4)
__device__ __forceinline__ void split8(const float4 v0, const float4 v1,
                                       uint4& hi, uint4& lo) {
    const float f[8] = {v0.x, v0.y, v0.z, v0.w, v1.x, v1.y, v1.z, v1.w};
    uint32_t h[4], l[4];
#pragma unroll
    for (int i = 0; i < 4; i++) {
        __nv_bfloat162 hh = __float22bfloat162_rn(make_float2(f[2*i], f[2*i+1]));
        float2 hf = __bfloat1622float2(hh);
        __nv_bfloat162 ll = __float22bfloat162_rn(
            make_float2(f[2*i] - hf.x, f[2*i+1] - hf.y));
        h[i] = *(uint32_t*)&hh;
        l[i] = *(uint32_t*)&ll;
    }
    hi = make_uint4(h[0], h[1], h[2], h[3]);
    lo = make_uint4(l[0], l[1], l[2], l[3]);
}

// cp.async (16B, L2-only)
#define CP16(smem_addr, gptr) \
    asm volatile("cp.async.cg.shared.global [%0], [%1], 16;" :: "r"(smem_addr), "l"(gptr))
#define CP_COMMIT() asm volatile("cp.async.commit_group;" ::: "memory")
#define CP_WAIT1()  asm volatile("cp.async.wait_group 1;" ::: "memory")

// ============================================================================
// Kernel 1/4: C[M,N] = A[M,K] @ W[N,K]^T via bf16x3 mma.sync (unchanged R4).
// ============================================================================
#define GSTAGE_BYTES 32768
#define GEMM_SMEM (2 * GSTAGE_BYTES)

__global__ void __launch_bounds__(256, 1) gemm_bf16x3_kernel(
    const float* __restrict__ A, const float* __restrict__ W,
    float* __restrict__ C, int N, int K)
{
    extern __shared__ char smem[];
    const uint32_t sb = smem_u32(smem);
    const int tid = threadIdx.x;
    const int wid = tid >> 5;
    const int lane = tid & 31;
    const int m0 = blockIdx.y * 128;
    const int n0 = blockIdx.x * 128;
    const int NC = K >> 5;

    const int warp_m = wid & 3;
    const int warp_n = wid >> 2;

    const int lrow = tid >> 1;
    const int lcg = (tid & 1) * 16;
    const float* Ag = A + (size_t)(m0 + lrow) * K + lcg;
    const float* Wg = W + (size_t)(n0 + lrow) * K + lcg;
    const int swz_l = (lrow >> 1) & 3;
    const uint32_t so0 = lrow * 64 + ((((tid & 1) * 2 + 0) ^ swz_l) << 4);
    const uint32_t so1 = lrow * 64 + ((((tid & 1) * 2 + 1) ^ swz_l) << 4);

    uint32_t aoff[2][2];
#pragma unroll
    for (int tm = 0; tm < 2; tm++) {
        int r = warp_m * 32 + tm * 16 + (lane & 15);
        int sw = (r >> 1) & 3;
#pragma unroll
        for (int ks = 0; ks < 2; ks++) {
            int ch = ks * 2 + (lane >> 4);
            aoff[tm][ks] = r * 64 + ((ch ^ sw) << 4);
        }
    }
    uint32_t boff[4][2];
#pragma unroll
    for (int bp = 0; bp < 4; bp++) {
        int r = warp_n * 64 + bp * 16 + ((lane >> 4) << 3) + (lane & 7);
        int sw = (r >> 1) & 3;
#pragma unroll
        for (int ks = 0; ks < 2; ks++) {
            int ch = ks * 2 + ((lane >> 3) & 1);
            boff[bp][ks] = r * 64 + ((ch ^ sw) << 4);
        }
    }

    float acc[2][8][4];
#pragma unroll
    for (int i = 0; i < 2; i++)
#pragma unroll
        for (int j = 0; j < 8; j++)
#pragma unroll
            for (int q = 0; q < 4; q++) acc[i][j][q] = 0.f;

    float4 ra[4], rw[4];

    auto ldg_stage = [&](int s) {
        const float* ap = Ag + s * 32;
        const float* wp = Wg + s * 32;
#pragma unroll
        for (int j = 0; j < 4; j++) ra[j] = *(const float4*)(ap + 4 * j);
#pragma unroll
        for (int j = 0; j < 4; j++) rw[j] = *(const float4*)(wp + 4 * j);
    };
    auto sts_stage = [&](int buf) {
        const uint32_t base = buf * GSTAGE_BYTES;
        uint4 hi, lo;
        split8(ra[0], ra[1], hi, lo);
        *(uint4*)(smem + base + 0 + so0) = hi;
        *(uint4*)(smem + base + 8192 + so0) = lo;
        split8(ra[2], ra[3], hi, lo);
        *(uint4*)(smem + base + 0 + so1) = hi;
        *(uint4*)(smem + base + 8192 + so1) = lo;
        split8(rw[0], rw[1], hi, lo);
        *(uint4*)(smem + base + 16384 + so0) = hi;
        *(uint4*)(smem + base + 24576 + so0) = lo;
        split8(rw[2], rw[3], hi, lo);
        *(uint4*)(smem + base + 16384 + so1) = hi;
        *(uint4*)(smem + base + 24576 + so1) = lo;
    };

    auto compute = [&](int buf) {
        const uint32_t ah = sb + buf * GSTAGE_BYTES;
        const uint32_t al = ah + 8192;
        const uint32_t wh = ah + 16384;
        const uint32_t wl = ah + 24576;
#pragma unroll
        for (int ks = 0; ks < 2; ks++) {
            uint32_t fa[2][4], fal[2][4];
#pragma unroll
            for (int tm = 0; tm < 2; tm++) {
                ldsm4(fa[tm], ah + aoff[tm][ks]);
                ldsm4(fal[tm], al + aoff[tm][ks]);
            }
            uint32_t fb[8][2], fbl[8][2];
#pragma unroll
            for (int bp = 0; bp < 4; bp++) {
                uint32_t t[4];
                ldsm4(t, wh + boff[bp][ks]);
                fb[2*bp][0] = t[0]; fb[2*bp][1] = t[1];
                fb[2*bp+1][0] = t[2]; fb[2*bp+1][1] = t[3];
                ldsm4(t, wl + boff[bp][ks]);
                fbl[2*bp][0] = t[0]; fbl[2*bp][1] = t[1];
                fbl[2*bp+1][0] = t[2]; fbl[2*bp+1][1] = t[3];
            }
#pragma unroll
            for (int tm = 0; tm < 2; tm++)
#pragma unroll
                for (int tn = 0; tn < 8; tn++) {
                    mma_bf16(acc[tm][tn], fa[tm], fb[tn]);
                    mma_bf16(acc[tm][tn], fal[tm], fb[tn]);
                    mma_bf16(acc[tm][tn], fa[tm], fbl[tn]);
                }
        }
    };

    ldg_stage(0);
    sts_stage(0);
    if (NC > 1) ldg_stage(1);
    __syncthreads();

#pragma unroll 1
    for (int bk = 0; bk < NC; bk++) {
        const int buf = bk & 1;
        if (bk + 1 < NC) sts_stage(buf ^ 1);
        if (bk + 2 < NC) ldg_stage(bk + 2);
        compute(buf);
        __syncthreads();
    }

    const int er = lane >> 2;
    const int ec = (lane & 3) * 2;
#pragma unroll
    for (int tm = 0; tm < 2; tm++) {
        const int rbase = m0 + warp_m * 32 + tm * 16 + er;
#pragma unroll
        for (int tn = 0; tn < 8; tn++) {
            const int cbase = n0 + warp_n * 64 + tn * 8 + ec;
            float* p0 = C + (size_t)rbase * N + cbase;
            float* p1 = C + (size_t)(rbase + 8) * N + cbase;
            *(float2*)p0 = make_float2(acc[tm][tn][0], acc[tm][tn][1]);
            *(float2*)p1 = make_float2(acc[tm][tn][2], acc[tm][tn][3]);
        }
    }
}

// ============================================================================
// Kernel 2: qk-norm + RoPE2D + transpose -> bf16 hi/lo outputs.
// q gets 0.125 (score scale) * log2(e) folded in (softmax uses exp2).
// v written transposed [b,g,d,l].
// ============================================================================
__global__ void __launch_bounds__(256) norm_rope_kernel(
    const float* __restrict__ qkv,
    __nv_bfloat16* __restrict__ qh, __nv_bfloat16* __restrict__ ql,
    __nv_bfloat16* __restrict__ kh, __nv_bfloat16* __restrict__ kl,
    __nv_bfloat16* __restrict__ vth, __nv_bfloat16* __restrict__ vtl)
{
    const int gwarp = (blockIdx.x * blockDim.x + threadIdx.x) >> 5;
    const int lane = threadIdx.x & 31;
    const int NVEC = MROWS * 24;
    if (gwarp >= NVEC) return;

    const int bl = gwarp / 24;
    const int slot = gwarp % 24;
    const int b = bl >> 10;
    const int l = bl & 1023;

    const float2 xv = *(const float2*)(qkv + (size_t)bl * QKV_E + slot * 64 + 2 * lane);
    float x1 = xv.x, x2 = xv.y;

    if (slot < 20) {
        float ss = x1 * x1 + x2 * x2;
#pragma unroll
        for (int o = 16; o > 0; o >>= 1)
            ss += __shfl_xor_sync(0xffffffffu, ss, o);
        float inv = 1.f / (sqrtf(ss) + 1e-10f);
        if (slot < 16) inv *= 0.18033688011112042f;  // 0.125 * log2(e)
        x1 *= inv; x2 *= inv;

        float psum = (float)((l >> 5) + (l & 31));
        float invfreq = exp2f(-0.41524101186098287f * (float)lane);
        float fr = psum * invfreq;
        float s, c;
        sincosf(fr, &s, &c);
        float olo = x1 * c - x2 * s;
        float ohi = x1 * s + x2 * c;

        __nv_bfloat16 *dh, *dl;
        if (slot < 16) {
            size_t base = (((size_t)b * NH + slot) * L_SZ + l) * HD;
            dh = qh + base; dl = ql + base;
        } else {
            size_t base = (((size_t)b * NG + (slot - 16)) * L_SZ + l) * HD;
            dh = kh + base; dl = kl + base;
        }
        __nv_bfloat16 h, lo;
        split1(olo, h, lo); dh[lane] = h; dl[lane] = lo;
        split1(ohi, h, lo); dh[lane + 32] = h; dl[lane + 32] = lo;
    } else {
        const int sv = slot - 20;
        const size_t base = ((size_t)b * NG + sv) * HD * L_SZ;
        __nv_bfloat16 h, lo;
        split1(x1, h, lo);
        vth[base + (size_t)(2 * lane) * L_SZ + l] = h;
        vtl[base + (size_t)(2 * lane) * L_SZ + l] = lo;
        split1(x2, h, lo);
        vth[base + (size_t)(2 * lane + 1) * L_SZ + l] = h;
        vtl[base + (size_t)(2 * lane + 1) * L_SZ + l] = lo;
    }
}

// ============================================================================
// Kernel 3: tensor-core flash attention (bf16x3 mma.sync).
// CTA: 128 q-rows x one (b,h). 8 warps, 16 q-rows each. K-chunks of 64 keys,
// 2-stage cp.async. S and P live in registers; softmax in-register (exp2).
// Q smem: [128 r][64 d] hi+lo. K chunk: [64 key][64 d]. V chunk: [64 d][64 key]
// (from transposed global), all 128B rows with chunk-XOR swizzle.
// ============================================================================
#define A_OFF_QH 0
#define A_OFF_QL 16384
#define A_OFF_KV 32768
#define A_STAGE  32768      // KH 8K | KL 8K | VH 8K | VL 8K
#define ATTN_SMEM (A_OFF_KV + 2 * A_STAGE)   // 96KB

__global__ void __launch_bounds__(256, 1) attn_mma_kernel(
    const __nv_bfloat16* __restrict__ qh, const __nv_bfloat16* __restrict__ ql,
    const __nv_bfloat16* __restrict__ kh, const __nv_bfloat16* __restrict__ kl,
    const __nv_bfloat16* __restrict__ vth, const __nv_bfloat16* __restrict__ vtl,
    float* __restrict__ O)
{
    extern __shared__ char smem[];
    const uint32_t sb = smem_u32(smem);
    const int tid = threadIdx.x;
    const int wid = tid >> 5;
    const int lane = tid & 31;

    const int qt = blockIdx.x;
    const int h = blockIdx.y;
    const int b = blockIdx.z;
    const int g = h >> 2;

    const __nv_bfloat16* Qh_g = qh + ((((size_t)b * NH + h) * L_SZ) + qt * 128) * HD;
    const __nv_bfloat16* Ql_g = ql + ((((size_t)b * NH + h) * L_SZ) + qt * 128) * HD;
    const __nv_bfloat16* Kh_g = kh + (((size_t)b * NG + g) * L_SZ) * HD;
    const __nv_bfloat16* Kl_g = kl + (((size_t)b * NG + g) * L_SZ) * HD;
    const __nv_bfloat16* Vth_g = vth + ((size_t)b * NG + g) * HD * L_SZ;
    const __nv_bfloat16* Vtl_g = vtl + ((size_t)b * NG + g) * HD * L_SZ;

    // ---- issue Q (once) ----
#pragma unroll
    for (int i = 0; i < 4; i++) {
        int idx = tid * 4 + i;            // 1024 chunks
        int row = idx >> 3, ch = idx & 7;
        uint32_t sw = (uint32_t)(row * 128 + ((ch ^ (row & 7)) << 4));
        CP16(sb + A_OFF_QH + sw, Qh_g + row * 64 + ch * 8);
        CP16(sb + A_OFF_QL + sw, Ql_g + row * 64 + ch * 8);
    }

    auto issue_chunk = [&](int c, int st) {
        const uint32_t base = sb + A_OFF_KV + st * A_STAGE;
#pragma unroll
        for (int i = 0; i < 2; i++) {
            int idx = tid * 2 + i;        // 512 chunks per buffer
            int row = idx >> 3, ch = idx & 7;
            uint32_t sw = (uint32_t)(row * 128 + ((ch ^ (row & 7)) << 4));
            CP16(base + sw,         Kh_g + (size_t)(c * 64 + row) * 64 + ch * 8);
            CP16(base + 8192 + sw,  Kl_g + (size_t)(c * 64 + row) * 64 + ch * 8);
            CP16(base + 16384 + sw, Vth_g + (size_t)row * L_SZ + c * 64 + ch * 8);
            CP16(base + 24576 + sw, Vtl_g + (size_t)row * L_SZ + c * 64 + ch * 8);
        }
    };

    issue_chunk(0, 0);
    CP_COMMIT();                          // group: Q + chunk0
    issue_chunk(1, 1);
    CP_COMMIT();                          // group: chunk1

    // ---- fragment address precompute ----
    uint32_t qoff[4];
#pragma unroll
    for (int ks = 0; ks < 4; ks++) {
        int r = wid * 16 + (lane & 15);
        int ch = ks * 2 + (lane >> 4);
        qoff[ks] = (uint32_t)(r * 128 + ((ch ^ (r & 7)) << 4));
    }
    uint32_t lbo[4][4];  // [rowpair16][kstep]  (shared by K and V buffers)
#pragma unroll
    for (int np = 0; np < 4; np++) {
        int r = np * 16 + ((lane >> 4) << 3) + (lane & 7);
#pragma unroll
        for (int ks = 0; ks < 4; ks++) {
            int ch = ks * 2 + ((lane >> 3) & 1);
            lbo[np][ks] = (uint32_t)(r * 128 + ((ch ^ (r & 7)) << 4));
        }
    }

    uint32_t qfh[4][4], qfl[4][4];
    float oacc[8][4];
#pragma unroll
    for (int t = 0; t < 8; t++)
#pragma unroll
        for (int q = 0; q < 4; q++) oacc[t][q] = 0.f;
    float mrow[2] = {-INFINITY, -INFINITY};
    float lrow[2] = {0.f, 0.f};

#pragma unroll 1
    for (int c = 0; c < 16; c++) {
        const int st = c & 1;
        CP_WAIT1();
        __syncthreads();

        if (c == 0) {
#pragma unroll
            for (int ks = 0; ks < 4; ks++) {
                ldsm4(qfh[ks], sb + A_OFF_QH + qoff[ks]);
                ldsm4(qfl[ks], sb + A_OFF_QL + qoff[ks]);
            }
        }

        const uint32_t kb = sb + A_OFF_KV + st * A_STAGE;
        const uint32_t vb = kb + 16384;

        // ---- S = Q K^T (scores in log2 domain; scale folded into q) ----
        float sacc[8][4];
#pragma unroll
        for (int t = 0; t < 8; t++)
#pragma unroll
            for (int q = 0; q < 4; q++) sacc[t][q] = 0.f;
#pragma unroll
        for (int ks = 0; ks < 4; ks++) {
#pragma unroll
            for (int np = 0; np < 4; np++) {
                uint32_t th[4], tl[4];
                ldsm4(th, kb + lbo[np][ks]);
                ldsm4(tl, kb + 8192 + lbo[np][ks]);
                mma_bf16(sacc[2*np],   qfh[ks], th);
                mma_bf16(sacc[2*np],   qfl[ks], th);
                mma_bf16(sacc[2*np],   qfh[ks], tl);
                mma_bf16(sacc[2*np+1], qfh[ks], th + 2);
                mma_bf16(sacc[2*np+1], qfl[ks], th + 2);
                mma_bf16(sacc[2*np+1], qfh[ks], tl + 2);
            }
        }

        // ---- online softmax (rows: lane/4 and lane/4+8) ----
#pragma unroll
        for (int r = 0; r < 2; r++) {
            float mx = mrow[r];
#pragma unroll
            for (int t = 0; t < 8; t++)
                mx = fmaxf(mx, fmaxf(sacc[t][2*r], sacc[t][2*r+1]));
            mx = fmaxf(mx, __shfl_xor_sync(0xffffffffu, mx, 1));
            mx = fmaxf(mx, __shfl_xor_sync(0xffffffffu, mx, 2));
            const float sc = exp2f(mrow[r] - mx);
            mrow[r] = mx;
            float sum = 0.f;
#pragma unroll
            for (int t = 0; t < 8; t++) {
                float p0 = exp2f(sacc[t][2*r]   - mx);
                float p1 = exp2f(sacc[t][2*r+1] - mx);
                sacc[t][2*r] = p0; sacc[t][2*r+1] = p1;
                sum += p0 + p1;
            }
            sum += __shfl_xor_sync(0xffffffffu, sum, 1);
            sum += __shfl_xor_sync(0xffffffffu, sum, 2);
            lrow[r] = lrow[r] * sc + sum;
#pragma unroll
            for (int t = 0; t < 8; t++) {
                oacc[t][2*r] *= sc; oacc[t][2*r+1] *= sc;
            }
        }

        // ---- O += P V  (P fragments built from sacc; V^T from smem) ----
#pragma unroll
        for (int j = 0; j < 4; j++) {
            uint32_t pah[4], pal[4];
            split2(sacc[2*j][0],   sacc[2*j][1],   pah[0], pal[0]);
            split2(sacc[2*j][2],   sacc[2*j][3],   pah[1], pal[1]);
            split2(sacc[2*j+1][0], sacc[2*j+1][1], pah[2], pal[2]);
            split2(sacc[2*j+1][2], sacc[2*j+1][3], pah[3], pal[3]);
#pragma unroll
            for (int dp = 0; dp < 4; dp++) {
                uint32_t th[4], tl[4];
                ldsm4(th, vb + lbo[dp][j]);
                ldsm4(tl, vb + 8192 + lbo[dp][j]);
                mma_bf16(oacc[2*dp],   pah, th);
                mma_bf16(oacc[2*dp],   pal, th);
                mma_bf16(oacc[2*dp],   pah, tl);
                mma_bf16(oacc[2*dp+1], pah, th + 2);
                mma_bf16(oacc[2*dp+1], pal, th + 2);
                mma_bf16(oacc[2*dp+1], pah, tl + 2);
            }
        }

        __syncthreads();
        if (c + 2 < 16) issue_chunk(c + 2, st);
        CP_COMMIT();
    }

    // ---- normalize + write O to [b, l, h*64+d] fp32 ----
    const float inv0 = 1.f / lrow[0];
    const float inv1 = 1.f / lrow[1];
    const int q0 = qt * 128 + wid * 16 + (lane >> 2);
#pragma unroll
    for (int t = 0; t < 8; t++) {
        const int col = h * 64 + t * 8 + (lane & 3) * 2;
        float* p0 = O + ((size_t)(b * L_SZ + q0)) * DM + col;
        float* p1 = O + ((size_t)(b * L_SZ + q0 + 8)) * DM + col;
        *(float2*)p0 = make_float2(oacc[t][0] * inv0, oacc[t][1] * inv0);
        *(float2*)p1 = make_float2(oacc[t][2] * inv1, oacc[t][3] * inv1);
    }
}

// ============================================================================
// launch
// ============================================================================
extern "C" void kernel_launch(void* const* d_in, const int* in_sizes, int n_in,
                              void* d_out, int out_size)
{
    const float* x     = (const float*)d_in[0];
    const float* w_qkv = (const float*)d_in[1];
    const float* w_o   = (const float*)d_in[2];
    float* out = (float*)d_out;

    float *qkv_p, *attn_p;
    __nv_bfloat16 *qh_p, *ql_p, *kh_p, *kl_p, *vth_p, *vtl_p;
    cudaGetSymbolAddress((void**)&qkv_p,  g_qkv);
    cudaGetSymbolAddress((void**)&attn_p, g_attn);
    cudaGetSymbolAddress((void**)&qh_p,  g_qh);
    cudaGetSymbolAddress((void**)&ql_p,  g_ql);
    cudaGetSymbolAddress((void**)&kh_p,  g_kh);
    cudaGetSymbolAddress((void**)&kl_p,  g_kl);
    cudaGetSymbolAddress((void**)&vth_p, g_vth);
    cudaGetSymbolAddress((void**)&vtl_p, g_vtl);

    cudaFuncSetAttribute(gemm_bf16x3_kernel,
                         cudaFuncAttributeMaxDynamicSharedMemorySize, GEMM_SMEM);
    cudaFuncSetAttribute(attn_mma_kernel,
                         cudaFuncAttributeMaxDynamicSharedMemorySize, ATTN_SMEM);

    // 1) QKV projection
    {
        dim3 grid(QKV_E / 128, MROWS / 128);
        gemm_bf16x3_kernel<<<grid, 256, GEMM_SMEM>>>(x, w_qkv, qkv_p, QKV_E, DM);
    }

    // 2) norm + rope -> bf16 hi/lo (v transposed)
    {
        int nvec = MROWS * 24;
        int blocks = (nvec + 7) / 8;
        norm_rope_kernel<<<blocks, 256>>>(qkv_p, qh_p, ql_p, kh_p, kl_p, vth_p, vtl_p);
    }

    // 3) attention (tensor cores)
    {
        dim3 grid(L_SZ / 128, NH, B_SZ);
        attn_mma_kernel<<<grid, 256, ATTN_SMEM>>>(qh_p, ql_p, kh_p, kl_p,
                                                  vth_p, vtl_p, attn_p);
    }

    // 4) output projection
    {
        dim3 grid(DM / 128, MROWS / 128);
        gemm_bf16x3_kernel<<<grid, 256, GEMM_SMEM>>>(attn_p, w_o, out, DM, DM);
    }
}